// round 17
// baseline (speedup 1.0000x reference)
#include <cuda_runtime.h>
#include <cstdint>

typedef unsigned long long ull;

__device__ __forceinline__ ull pack2(float a, float b) {
    ull r; asm("mov.b64 %0,{%1,%2};" : "=l"(r) : "f"(a), "f"(b)); return r;
}
__device__ __forceinline__ void fma2(ull& d, ull a, ull b) {
    asm("fma.rn.f32x2 %0,%1,%2,%3;" : "=l"(d) : "l"(a), "l"(b), "l"(d));
}
__device__ __forceinline__ void add2(ull& d, ull a) {
    asm("add.rn.f32x2 %0,%1,%2;" : "=l"(d) : "l"(d), "l"(a));
}
__device__ __forceinline__ float lo2(ull a) { return __uint_as_float((unsigned)a); }
__device__ __forceinline__ float hi2(ull a) { return __uint_as_float((unsigned)(a >> 32)); }

#define CH 8                    // h rows per block (56 = 7 * 8)
#define XT_BYTES 19200          // bytes per x-tile buffer (both halves)

struct Smem {
    union {
        float xtile[3][2][2][2][10][60];  // [buf][half][kqs][n][slot][w]  57600 B
        ull   pbuf[4][112][17];           // partials, alias               60928 B
    } u;
    float S[2][CH][4][60];       // [n][h][o][x] = t4[x-1], 0 pad at 0,57
    ull   w1p[768];              // [k][i][o] packed (w,w)
    ull   w2p[192];              // [i][kk][j] packed (w,w)
};
#define SMEM_BYTES sizeof(Smem)  // 83968 -> 2 blocks/SM

// R15 (half-block pipelines) with a slimmer epilogue path: t4 lives ONLY in
// the shifted array S; phase 2 reads 6 contiguous floats per (i,h) with one
// LDS.128 + one LDS.64 and builds the two straddling w-tap pairs in
// registers (pack2), halving phase-2 smem-tap traffic and dropping M.
__global__ __launch_bounds__(448, 2) void fused_kernel(
    const float* __restrict__ x, const float* __restrict__ w1,
    const float* __restrict__ w2, float* __restrict__ out)
{
    extern __shared__ __align__(16) char smraw[];
    Smem& sm = *reinterpret_cast<Smem*>(smraw);

    const int tid  = threadIdx.x;
    const int half = tid / 224;
    const int htid = tid % 224;
    const int h0   = blockIdx.x * CH;
    const int l    = blockIdx.y;

    // ---- per-thread cp.async descriptors: 3 quads within OWN half ----
    const char* xl = reinterpret_cast<const char*>(x) + (size_t)l * 128 * 12544;
    unsigned qoff[3]; unsigned qdst[3]; unsigned qszbits = 0;
#pragma unroll
    for (int i = 0; i < 3; i++) {
        int q   = htid + i * 224;
        int qq  = (q < 560) ? q : 0;
        int kqs = qq / 280, r = qq % 280;
        int n = r / 140, s = (r / 14) % 10, wq = r % 14;
        int hv  = h0 - 1 + s;                 // virtual (rolled) tap row
        int inr = (hv >= 0 && hv < 56);
        int row = (hv == 0) ? 55 : hv - 1;
        int ch0 = 64 * half + 32 * kqs + n;   // channel at t = 0  (c = 32kq+2t+n)
        qoff[i] = (unsigned)(ch0 * 12544 + (inr ? row * 224 : 0) + wq * 16);
        qdst[i] = (unsigned)__cvta_generic_to_shared(&sm.u.xtile[0][half][kqs][n][s][wq * 4]);
        qszbits |= (unsigned)inr << i;
    }

    auto issue = [&](int t) {
        unsigned bofs = (unsigned)((t % 3) * XT_BYTES);
        unsigned cofs = (unsigned)(t * 25088);     // +2 channels per tile
#pragma unroll
        for (int i = 0; i < 3; i++) {
            if (i == 2 && htid >= 112) break;
            int sz = (int)((qszbits >> i) & 1u) * 16;
            asm volatile("cp.async.cg.shared.global [%0], [%1], 16, %2;"
                         :: "r"(qdst[i] + bofs), "l"(xl + qoff[i] + cofs), "r"(sz)
                         : "memory");
        }
        asm volatile("cp.async.commit_group;" ::: "memory");
    };

    issue(0); issue(1);                  // prologue: 2 tiles in flight per half

    for (int idx = tid; idx < 768; idx += 448) { float v = w1[idx]; sm.w1p[idx] = pack2(v, v); }
    if (tid < 192) { float v = w2[tid]; sm.w2p[tid] = pack2(v, v); }
    if (tid < 128) {   // zero pad cells of S: x = 0 and x = 57
        int n = tid >> 6, rem = tid & 63, h = rem >> 3, o = (rem >> 1) & 3;
        sm.S[n][h][o][(tid & 1) ? 57 : 0] = 0.f;
    }
    __syncthreads();                     // weights/pads cross halves: one block sync

    // ---------------- Phase 1: two independent half-pipelines ----------------
    const int kq  = tid / 112;           // = 2*half + kqs
    const int kqs = kq & 1;
    const int rem = tid % 112;
    const int n   = rem / 56;
    const int hp  = (rem / 14) % 4;
    const int wq  = rem % 14;
    const int w0  = wq * 4;

    ull acc[2][4][2];
#pragma unroll
    for (int h = 0; h < 2; h++)
#pragma unroll
        for (int o = 0; o < 4; o++) { acc[h][o][0] = 0ull; acc[h][o][1] = 0ull; }

    for (int t = 0; t < 16; t++) {
        if (t < 15) asm volatile("cp.async.wait_group 1;" ::: "memory");
        else        asm volatile("cp.async.wait_group 0;" ::: "memory");
        asm volatile("bar.sync %0, 224;" :: "r"(1 + half) : "memory");
                                         // tile t visible to this half; buf(t+2)%3 free
        if (t + 2 < 16) issue(t + 2);    // overwrites buffer last read at t-1

        const float* xb = &sm.u.xtile[t % 3][half][kqs][n][0][0];
        ulonglong2 v[4];
#pragma unroll
        for (int r = 0; r < 4; r++)
            v[r] = *reinterpret_cast<const ulonglong2*>(xb + (hp * 2 + r) * 60 + w0);

        const ulonglong2* wk = reinterpret_cast<const ulonglong2*>(&sm.w1p[(kq * 16 + t) * 12]);
#pragma unroll
        for (int p = 0; p < 6; p++) {
            ulonglong2 wv = wk[p];
            const int e0 = 2 * p,     i0 = e0 >> 2, o0 = e0 & 3;
            const int e1 = 2 * p + 1, i1 = e1 >> 2, o1 = e1 & 3;
            fma2(acc[0][o0][0], v[i0].x,     wv.x);
            fma2(acc[0][o0][1], v[i0].y,     wv.x);
            fma2(acc[1][o0][0], v[i0 + 1].x, wv.x);
            fma2(acc[1][o0][1], v[i0 + 1].y, wv.x);
            fma2(acc[0][o1][0], v[i1].x,     wv.y);
            fma2(acc[0][o1][1], v[i1].y,     wv.y);
            fma2(acc[1][o1][0], v[i1 + 1].x, wv.y);
            fma2(acc[1][o1][1], v[i1 + 1].y, wv.y);
        }
    }
    __syncthreads();                     // both halves done -> pbuf alias safe

    // publish partials
    {
        ull* dst = &sm.u.pbuf[kq][rem][0];
#pragma unroll
        for (int h = 0; h < 2; h++)
#pragma unroll
            for (int o = 0; o < 4; o++)
#pragma unroll
                for (int wp = 0; wp < 2; wp++)
                    dst[(h * 4 + o) * 2 + wp] = acc[h][o][wp];
    }
    __syncthreads();

    // parallel reduction + t4 smem write (shifted form only): thread = (item, o)
    {
        const int it = tid % 112;
        const int o2 = tid / 112;
        ull s[2][2];
#pragma unroll
        for (int h = 0; h < 2; h++)
#pragma unroll
            for (int wp = 0; wp < 2; wp++)
                s[h][wp] = sm.u.pbuf[0][it][(h * 4 + o2) * 2 + wp];
#pragma unroll
        for (int q = 1; q < 4; q++)
#pragma unroll
            for (int h = 0; h < 2; h++)
#pragma unroll
                for (int wp = 0; wp < 2; wp++)
                    add2(s[h][wp], sm.u.pbuf[q][it][(h * 4 + o2) * 2 + wp]);

        const int rn  = it / 56;
        const int rhp = (it / 14) % 4;
        const int rw0 = (it % 14) * 4;
#pragma unroll
        for (int h = 0; h < 2; h++) {
            const int hr = rhp * 2 + h;
            sm.S[rn][hr][o2][rw0 + 1] = lo2(s[h][0]);
            *reinterpret_cast<ull*>(&sm.S[rn][hr][o2][rw0 + 2]) = pack2(hi2(s[h][0]), lo2(s[h][1]));
            sm.S[rn][hr][o2][rw0 + 4] = hi2(s[h][1]);
        }
    }
    __syncthreads();

    // ---------------- Phase 2 ----------------
    {
        const int tx = tid % 14;
        const int ty = tid / 14;
        const int o  = ty >> 3;
        const int j0 = (ty & 7) * 4;
        const int pw0 = tx * 4;

        for (int h = 0; h < CH; h++) {
            ull acc2[4][2];
#pragma unroll
            for (int jj = 0; jj < 4; jj++) { acc2[jj][0] = 0ull; acc2[jj][1] = 0ull; }

#pragma unroll
            for (int i = 0; i < 2; i++) {
                // 6 floats t4[pw0-1 .. pw0+4] = S[pw0 .. pw0+5]: LDS.128 + LDS.64
                ulonglong2 q = *reinterpret_cast<const ulonglong2*>(&sm.S[i][h][o][pw0]);
                ull        r = *reinterpret_cast<const ull*>(&sm.S[i][h][o][pw0 + 4]);
                ull m0 = pack2(hi2(q.x), lo2(q.y));   // (t4[pw0],   t4[pw0+1])
                ull m1 = pack2(hi2(q.y), lo2(r));     // (t4[pw0+2], t4[pw0+3])
#pragma unroll
                for (int kk = 0; kk < 3; kk++) {
                    ull p0, p1;
                    if (kk == 0)      { p0 = q.x; p1 = q.y; }
                    else if (kk == 1) { p0 = m0;  p1 = m1;  }
                    else              { p0 = q.y; p1 = r;   }
                    ulonglong2 Wa = *reinterpret_cast<const ulonglong2*>(&sm.w2p[i * 96 + kk * 32 + j0]);
                    ulonglong2 Wb = *reinterpret_cast<const ulonglong2*>(&sm.w2p[i * 96 + kk * 32 + j0 + 2]);
                    fma2(acc2[0][0], p0, Wa.x); fma2(acc2[0][1], p1, Wa.x);
                    fma2(acc2[1][0], p0, Wa.y); fma2(acc2[1][1], p1, Wa.y);
                    fma2(acc2[2][0], p0, Wb.x); fma2(acc2[2][1], p1, Wb.x);
                    fma2(acc2[3][0], p0, Wb.y); fma2(acc2[3][1], p1, Wb.y);
                }
            }

#pragma unroll
            for (int jj = 0; jj < 4; jj++) {
                int cc = (j0 + jj) * 4 + o;
                float4* p = reinterpret_cast<float4*>(
                    out + ((size_t)l * 128 + cc) * 3136 + (h0 + h) * 56 + pw0);
                *p = make_float4(lo2(acc2[jj][0]), hi2(acc2[jj][0]),
                                 lo2(acc2[jj][1]), hi2(acc2[jj][1]));
            }
        }
    }
}

extern "C" void kernel_launch(void* const* d_in, const int* in_sizes, int n_in,
                              void* d_out, int out_size)
{
    const float* x  = (const float*)d_in[0];
    const float* w1 = (const float*)d_in[1];
    const float* w2 = (const float*)d_in[2];
    float* out = (float*)d_out;

    cudaFuncSetAttribute(fused_kernel, cudaFuncAttributeMaxDynamicSharedMemorySize,
                         (int)SMEM_BYTES);
    fused_kernel<<<dim3(7, 128), 448, SMEM_BYTES>>>(x, w1, w2, out);
}